// round 2
// baseline (speedup 1.0000x reference)
#include <cuda_runtime.h>
#include <cuda_bf16.h>

#define WS 7
#define DROP_PROB 0.1f
#define H 256
#define W 256
#define HC (H - WS + 1)   // 250
#define WC (W - WS + 1)   // 250
#define BC (16 * 64)      // batch * channels = 1024

// Scratch: the [H, W] drop mask, shared across all batch/channel images.
// 256*256 floats = 256 KB — lives in L2 during the multiply kernel.
__device__ float g_mask[H * W];

// ---------------------------------------------------------------------------
// Kernel 1: dilate anchor decisions (u < p) with a ws x ws max window.
// Pixel (h, w) is dropped iff any anchor in [h-ws+1, h] x [w-ws+1, w]
// (clamped to the valid anchor grid [0,HC) x [0,WC)) has u < DROP_PROB.
// 65536 threads, up to 49 reads of the tiny L2-resident u each. Negligible.
// ---------------------------------------------------------------------------
__global__ void build_mask_kernel(const float* __restrict__ u) {
    int idx = blockIdx.x * blockDim.x + threadIdx.x;
    if (idx >= H * W) return;
    int h = idx >> 8;       // / 256
    int w = idx & 255;      // % 256

    int ah0 = h - (WS - 1); if (ah0 < 0) ah0 = 0;
    int ah1 = h;            if (ah1 > HC - 1) ah1 = HC - 1;
    int aw0 = w - (WS - 1); if (aw0 < 0) aw0 = 0;
    int aw1 = w;            if (aw1 > WC - 1) aw1 = WC - 1;

    int dropped = 0;
    for (int ah = ah0; ah <= ah1; ++ah) {
        const float* __restrict__ urow = u + ah * WC;
        #pragma unroll 7
        for (int aw = aw0; aw <= aw1; ++aw) {
            dropped |= (urow[aw] < DROP_PROB);
        }
    }
    g_mask[idx] = dropped ? 0.0f : 1.0f;
}

// ---------------------------------------------------------------------------
// Kernel 2: out = x * mask, streamed as float4.
// Per image there are H*W/4 = 16384 float4s, so the mask float4 index for
// global float4 index i is simply (i & 16383) — one AND, no div/mod.
// Mask (256 KB) is L2-resident -> the only DRAM traffic is x in + out.
// ---------------------------------------------------------------------------
__global__ void apply_mask_kernel(const float4* __restrict__ x,
                                  float4* __restrict__ out,
                                  int n4) {
    const float4* __restrict__ mask4 = reinterpret_cast<const float4*>(g_mask);
    int stride = gridDim.x * blockDim.x;
    for (int i = blockIdx.x * blockDim.x + threadIdx.x; i < n4; i += stride) {
        float4 xv = x[i];
        float4 mv = mask4[i & (H * W / 4 - 1)];
        float4 ov;
        ov.x = xv.x * mv.x;
        ov.y = xv.y * mv.y;
        ov.z = xv.z * mv.z;
        ov.w = xv.w * mv.w;
        out[i] = ov;
    }
}

extern "C" void kernel_launch(void* const* d_in, const int* in_sizes, int n_in,
                              void* d_out, int out_size) {
    const float* x = (const float*)d_in[0];   // [16, 64, 256, 256] fp32
    const float* u = (const float*)d_in[1];   // [250, 250] fp32
    float* out = (float*)d_out;

    // Kernel 1: build the shared mask (65536 pixels)
    build_mask_kernel<<<(H * W + 255) / 256, 256>>>(u);

    // Kernel 2: streaming multiply. 16M float4 total; grid-stride with
    // ~4 iterations per thread for memory-level parallelism.
    int n4 = BC * H * W / 4;                  // 16,777,216 float4
    int threads = 256;
    int blocks = 16384;                       // 4 float4 per thread
    apply_mask_kernel<<<blocks, threads>>>(
        reinterpret_cast<const float4*>(x),
        reinterpret_cast<float4*>(out), n4);
}